// round 14
// baseline (speedup 1.0000x reference)
#include <cuda_runtime.h>
#include <cuda_fp16.h>
#include <cstdint>

// InfluenceProp R14: R13 + (a) coup stored as fp16 (packed pair reuses the
// epilogue's existing pkf2 result; halves the 210MB round-trip), (b) prep_all
// parallelism doubled (vec blocks 8 samples, weight blocks 96).

#define K_N 50

// ---------------- gmem scratch ----------------
__device__ __align__(1024) __half g_wb[6 * 16384];   // 6 units x 128x128 fp16
__device__ float g_vec[2ull * 4096 * 128];           // folded biases [which][b][128]
__device__ __half g_coup[204800ull * 128];           // coup fp16 per global row
__device__ float g_score[204928];                    // raw scores per global row

// ---------------- smem byte offsets ----------------
#define SM_A     0          // 128x128 fp16 swizzled (32KB)
#define SM_B0    32768      // 128x128 fp16 (32KB)
#define SM_B1    65536
#define SM_IDX   98304      // 128 ints
#define SM_BFUS  98816
#define SM_BC2   99328
#define SM_BA2   99840
#define SM_W3    100352
#define SM_VC1   100864     // [4][128] f
#define SM_VA1   102912     // [4][128] f
#define SM_TOTAL 104960

// tile layout: row r, 256 B/row; 16B chunk c stored at (c ^ (r&7))
__device__ __host__ __forceinline__ int tile_off(int r, int c) {
    return r * 256 + ((c ^ (r & 7)) << 4);
}

__device__ __forceinline__ uint32_t smem_u32(const void* p) {
    uint32_t a;
    asm("{ .reg .u64 t; cvta.to.shared.u64 t, %1; cvt.u32.u64 %0, t; }" : "=r"(a) : "l"(p));
    return a;
}

#define LDSM4(r0, r1, r2, r3, addr) \
    asm volatile("ldmatrix.sync.aligned.m8n8.x4.shared.b16 {%0,%1,%2,%3}, [%4];" \
                 : "=r"(r0), "=r"(r1), "=r"(r2), "=r"(r3) : "r"(addr))
#define MMA(ac, a0, a1, a2, a3, b0, b1) \
    asm volatile("mma.sync.aligned.m16n8k16.row.col.f32.f16.f16.f32 " \
                 "{%0,%1,%2,%3},{%4,%5,%6,%7},{%8,%9},{%0,%1,%2,%3};" \
                 : "+f"((ac)[0]), "+f"((ac)[1]), "+f"((ac)[2]), "+f"((ac)[3]) \
                 : "r"(a0), "r"(a1), "r"(a2), "r"(a3), "r"(b0), "r"(b1))

__device__ __forceinline__ uint32_t pkf2(float a, float b) {
    __half2 t = __floats2half2_rn(a, b);
    uint32_t u; __builtin_memcpy(&u, &t, 4);
    return u;
}

// ---------------- fused prepass: weights + folded bias vectors ----------------
__global__ void prep_all(
    const float* __restrict__ w_fus, const float* __restrict__ w_c1,
    const float* __restrict__ w_c2,  const float* __restrict__ w_a1,
    const float* __restrict__ w_a2,
    const float* __restrict__ i_embs, const float* __restrict__ u_embs,
    const float* __restrict__ b_c1,   const float* __restrict__ b_a1,
    int Btot)
{
    int bid = blockIdx.x;
    int tid = threadIdx.x;
    if (bid < 96) {
        // weight fp16 + transpose + swizzle (96 blocks = 6 units x 16 parts)
        int u = bid >> 4;
        int part = bid & 15;
        const float* base; int koff = 0;
        if      (u == 0) { base = w_fus; }
        else if (u == 1) { base = w_fus; koff = 128; }
        else if (u == 2) { base = w_c1; }
        else if (u == 3) { base = w_c2; }
        else if (u == 4) { base = w_a1; }
        else             { base = w_a2; }
        int e0 = part * 1024;
        for (int i = tid; i < 1024; i += blockDim.x) {
            int e = e0 + i;
            int n = e >> 7, k = e & 127;
            float v = base[(size_t)(k + koff) * 128 + n];
            int elem = (n * 256 + (((k >> 3) ^ (n & 7)) << 4) + (k & 7) * 2) >> 1;
            g_wb[(size_t)u * 16384 + elem] = __float2half_rn(v);
        }
        return;
    }
    // folded bias vectors: 8 samples per block
    __shared__ float sE[8 * 128];
    __shared__ float sW[32 * 128];
    int v = bid - 96;
    int which = v & 1;
    int bbase = (v >> 1) * 8;
    const float* emb = which ? u_embs : i_embs;
    const float* W   = (which ? w_a1 : w_c1) + (size_t)128 * 128;
    const float* bb  = which ? b_a1 : b_c1;

    for (int idx = tid; idx < 1024; idx += 256) {
        int s = idx >> 7, c = idx & 127;
        sE[idx] = (bbase + s < Btot) ? emb[(size_t)(bbase + s) * 128 + c] : 0.f;
    }
    int col = tid & 127;
    int sg  = tid >> 7;                 // samples sg*4 .. sg*4+3
    float acc[4];
#pragma unroll
    for (int j = 0; j < 4; ++j) acc[j] = bb[col];

    for (int kc = 0; kc < 4; ++kc) {
        __syncthreads();
        for (int idx = tid; idx < 4096; idx += 256)
            sW[idx] = W[(size_t)(kc * 32 + (idx >> 7)) * 128 + (idx & 127)];
        __syncthreads();
#pragma unroll 8
        for (int kk = 0; kk < 32; ++kk) {
            float w = sW[kk * 128 + col];
#pragma unroll
            for (int j = 0; j < 4; ++j)
                acc[j] = fmaf(sE[(sg * 4 + j) * 128 + kc * 32 + kk], w, acc[j]);
        }
    }
#pragma unroll
    for (int j = 0; j < 4; ++j) {
        int s = bbase + sg * 4 + j;
        if (s < Btot)
            g_vec[(size_t)which * Btot * 128 + (size_t)s * 128 + col] = acc[j];
    }
}

// ---------------- main kernel pieces ----------------
__device__ __forceinline__ void copy_unit(int u, uint32_t dstAddr, int tid) {
    const char* src = (const char*)g_wb + (size_t)u * 32768;
#pragma unroll
    for (int t = 0; t < 8; ++t) {
        int i = tid + t * 256;             // 0..2047 16B lines
        asm volatile("cp.async.cg.shared.global [%0], [%1], 16;"
                     :: "r"(dstAddr + i * 16), "l"(src + (size_t)i * 16));
    }
    asm volatile("cp.async.commit_group;" ::: "memory");
}

// single-term sweep over K=128: warp w owns rows [16w,16w+16) x full N=128.
__device__ __forceinline__ void sweep(
    float (&acc)[16][4],
    uint32_t aT, uint32_t bB,
    int w, int l)
{
    const int rA = 16 * w + (l & 15);
    const uint32_t aRowOff = (uint32_t)rA * 256;
    const int axor = rA & 7;
    const int khA = l >> 4;
    const uint32_t bLane = (uint32_t)(((l >> 4) & 1) * 2048 + (l & 7) * 256);
    const int bKh  = (l >> 3) & 1;
    const int bxor = l & 7;

#pragma unroll 1
    for (int ks = 0; ks < 8; ++ks) {
        uint32_t aoff = aRowOff + (uint32_t)(((2 * ks + khA) ^ axor) << 4);
        uint32_t a0, a1, a2, a3;
        LDSM4(a0, a1, a2, a3, aT + aoff);

        uint32_t bko = bLane + (uint32_t)(((2 * ks + bKh) ^ bxor) << 4);

        uint32_t bh[8][2];
#pragma unroll
        for (int p = 0; p < 4; ++p)
            LDSM4(bh[2 * p][0], bh[2 * p][1], bh[2 * p + 1][0], bh[2 * p + 1][1],
                  bB + (uint32_t)p * 4096 + bko);
#pragma unroll
        for (int t = 0; t < 8; ++t)
            MMA(acc[t], a0, a1, a2, a3, bh[t][0], bh[t][1]);
#pragma unroll
        for (int p = 0; p < 4; ++p)
            LDSM4(bh[2 * p][0], bh[2 * p][1], bh[2 * p + 1][0], bh[2 * p + 1][1],
                  bB + (uint32_t)(p + 4) * 4096 + bko);
#pragma unroll
        for (int t = 0; t < 8; ++t)
            MMA(acc[t + 8], a0, a1, a2, a3, bh[t][0], bh[t][1]);
    }
}

// gather table rows -> fp16 -> swizzled A tile (all 128 local rows valid)
__device__ __forceinline__ void gatherA(
    const float* __restrict__ tbl, const int* sIdx, char* smemc, int tid)
{
    for (int idx = tid; idx < 2048; idx += 256) {
        int r = idx >> 4;
        int c = idx & 15;
        int u = sIdx[r];
        const float4* src = (const float4*)(tbl + (size_t)u * 128 + c * 8);
        float4 v0 = src[0], v1 = src[1];
        uint4 hv = make_uint4(pkf2(v0.x, v0.y), pkf2(v0.z, v0.w),
                              pkf2(v1.x, v1.y), pkf2(v1.z, v1.w));
        *(uint4*)(smemc + SM_A + tile_off(r, c)) = hv;
    }
}

// bias + relu -> fp16 back into A tile (opt: fp16 coup to gmem); resets acc.
// vec indexed by (global_sample - s_first) * vstride (vstride 0 = shared).
__device__ __forceinline__ void epilogueA(
    float (&acc)[16][4], char* smemc,
    const float* vec, int vstride,
    int gBase, int s_first,
    bool writeCoup, int w, int l)
{
    int q  = 16 * w + (l >> 2);
    int p2 = (l & 3) * 2;
    int r0 = q, r1 = q + 8;
    int s0 = (gBase + r0) / K_N - s_first;
    int s1 = (gBase + r1) / K_N - s_first;
    const float* bv0 = vec + s0 * vstride;
    const float* bv1 = vec + s1 * vstride;
    uint32_t* coup32 = (uint32_t*)g_coup;
#pragma unroll
    for (int t = 0; t < 16; ++t) {
        int n = 8 * t + p2;
        float y00 = fmaxf(acc[t][0] + bv0[n],     0.f);
        float y01 = fmaxf(acc[t][1] + bv0[n + 1], 0.f);
        float y10 = fmaxf(acc[t][2] + bv1[n],     0.f);
        float y11 = fmaxf(acc[t][3] + bv1[n + 1], 0.f);
        acc[t][0] = 0.f; acc[t][1] = 0.f; acc[t][2] = 0.f; acc[t][3] = 0.f;
        uint32_t h0 = pkf2(y00, y01);
        uint32_t h1 = pkf2(y10, y11);
        *(uint32_t*)(smemc + SM_A + tile_off(r0, t) + p2 * 2) = h0;
        *(uint32_t*)(smemc + SM_A + tile_off(r1, t) + p2 * 2) = h1;
        if (writeCoup) {
            coup32[(size_t)(gBase + r0) * 64 + (n >> 1)] = h0;
            coup32[(size_t)(gBase + r1) * 64 + (n >> 1)] = h1;
        }
    }
}

// last layer: bias+relu (shared ba2), dot w3, quad reduce -> g_score[global row]
__device__ __forceinline__ void epilogueScore(
    float (&acc)[16][4], const float* ba2, const float* w3, float b3,
    int gBase, int w, int l)
{
    int q  = 16 * w + (l >> 2);
    int p2 = (l & 3) * 2;
    float p0 = 0.f, p1 = 0.f;
#pragma unroll
    for (int t = 0; t < 16; ++t) {
        int n = 8 * t + p2;
        p0 = fmaf(fmaxf(acc[t][0] + ba2[n],     0.f), w3[n],     p0);
        p0 = fmaf(fmaxf(acc[t][1] + ba2[n + 1], 0.f), w3[n + 1], p0);
        p1 = fmaf(fmaxf(acc[t][2] + ba2[n],     0.f), w3[n],     p1);
        p1 = fmaf(fmaxf(acc[t][3] + ba2[n + 1], 0.f), w3[n + 1], p1);
    }
    p0 += __shfl_xor_sync(0xffffffffu, p0, 1);
    p0 += __shfl_xor_sync(0xffffffffu, p0, 2);
    p1 += __shfl_xor_sync(0xffffffffu, p1, 1);
    p1 += __shfl_xor_sync(0xffffffffu, p1, 2);
    if ((l & 3) == 0) {
        g_score[gBase + q]     = p0 + b3;
        g_score[gBase + q + 8] = p1 + b3;
    }
}

#define WAITG(n) asm volatile("cp.async.wait_group %0;" :: "n"(n) : "memory")

__global__ __launch_bounds__(256, 2)
void influence_main(
    const float* __restrict__ act_users_f,
    const float* __restrict__ emb_table, const float* __restrict__ prof_table,
    const float* __restrict__ b_fus, const float* __restrict__ b_c2,
    const float* __restrict__ b_a2,  const float* __restrict__ w_a3,
    const float* __restrict__ b_a3,
    int Btot)
{
    extern __shared__ char smemc[];
    const int tid = threadIdx.x;
    const int w = tid >> 5, l = tid & 31;
    const int gBase = blockIdx.x * 128;
    const int G = Btot * K_N;
    const int s_first = gBase / K_N;
    const int* act_users = (const int*)act_users_f;   // flat [B*50]
    uint32_t sb = smem_u32(smemc);

    int* sIdx     = (int*)(smemc + SM_IDX);
    float* sBfus  = (float*)(smemc + SM_BFUS);
    float* sBc2   = (float*)(smemc + SM_BC2);
    float* sBa2   = (float*)(smemc + SM_BA2);
    float* sW3    = (float*)(smemc + SM_W3);
    float* sVC1   = (float*)(smemc + SM_VC1);
    float* sVA1   = (float*)(smemc + SM_VA1);

    copy_unit(0, sb + SM_B0, tid);
    copy_unit(1, sb + SM_B1, tid);

    if (tid < 128) {
        int g = gBase + tid;
        sIdx[tid] = (g < G) ? act_users[g] : 0;
    } else {
        int c = tid - 128;
        sBfus[c] = b_fus[c];
        sBc2[c]  = b_c2[c];
        sBa2[c]  = b_a2[c];
        sW3[c]   = w_a3[c];
    }
    // stage up to 4 per-sample folded bias vectors
    for (int idx = tid; idx < 4 * 128; idx += 256) {
        int j = idx >> 7, c = idx & 127;
        int s = s_first + j; if (s > Btot - 1) s = Btot - 1;
        sVC1[idx] = g_vec[(size_t)s * 128 + c];
        sVA1[idx] = g_vec[(size_t)Btot * 128 + (size_t)s * 128 + c];
    }
    __syncthreads();                       // sIdx visible
    gatherA(emb_table, sIdx, smemc, tid);

    float acc[16][4];
#pragma unroll
    for (int t = 0; t < 16; ++t) {
        acc[t][0] = 0.f; acc[t][1] = 0.f; acc[t][2] = 0.f; acc[t][3] = 0.f;
    }

    WAITG(1); __syncthreads();             // A(emb) + unit0 ready
    sweep(acc, sb + SM_A, sb + SM_B0, w, l);
    __syncthreads();                       // B0 free, A free
    copy_unit(2, sb + SM_B0, tid);
    gatherA(prof_table, sIdx, smemc, tid);
    WAITG(1); __syncthreads();             // A(prof) + unit1 ready
    sweep(acc, sb + SM_A, sb + SM_B1, w, l);
    __syncthreads();                       // B1 free, A free
    copy_unit(3, sb + SM_B1, tid);
    epilogueA(acc, smemc, sBfus, 0, gBase, s_first, false, w, l);   // L1
    WAITG(1); __syncthreads();
    sweep(acc, sb + SM_A, sb + SM_B0, w, l);                        // L2
    __syncthreads();
    copy_unit(4, sb + SM_B0, tid);
    epilogueA(acc, smemc, sVC1, 128, gBase, s_first, false, w, l);  // L2 -> c1
    WAITG(1); __syncthreads();
    sweep(acc, sb + SM_A, sb + SM_B1, w, l);                        // L3
    __syncthreads();
    copy_unit(5, sb + SM_B1, tid);
    epilogueA(acc, smemc, sBc2, 0, gBase, s_first, true, w, l);     // L3 -> coup
    WAITG(1); __syncthreads();
    sweep(acc, sb + SM_A, sb + SM_B0, w, l);                        // L4
    __syncthreads();
    epilogueA(acc, smemc, sVA1, 128, gBase, s_first, false, w, l);  // L4 -> h
    WAITG(0); __syncthreads();
    sweep(acc, sb + SM_A, sb + SM_B1, w, l);                        // L5
    epilogueScore(acc, sBa2, sW3, b_a3[0], gBase, w, l);
}

// ---------------- finish: per-sample softmax + aggregation ----------------
__global__ __launch_bounds__(128)
void influence_finish(
    float* __restrict__ out_combined, float* __restrict__ out_att)
{
    __shared__ float sAtt[64];
    int s = blockIdx.x;
    int tid = threadIdx.x;
    int l = tid & 31;

    if (tid < 32) {
        float v1 = (l < K_N)      ? g_score[s * K_N + l]      : -1e30f;
        float v2 = (l + 32 < K_N) ? g_score[s * K_N + l + 32] : -1e30f;
        float m = fmaxf(v1, v2);
#pragma unroll
        for (int o = 16; o; o >>= 1)
            m = fmaxf(m, __shfl_xor_sync(0xffffffffu, m, o));
        float e1 = (l < K_N)      ? expf(v1 - m) : 0.f;
        float e2 = (l + 32 < K_N) ? expf(v2 - m) : 0.f;
        float sum = e1 + e2;
#pragma unroll
        for (int o = 16; o; o >>= 1)
            sum += __shfl_xor_sync(0xffffffffu, sum, o);
        float inv = 1.f / sum;
        if (l < K_N)      sAtt[l]      = e1 * inv;
        if (l + 32 < K_N) sAtt[l + 32] = e2 * inv;
    }
    __syncthreads();

    float a = 0.f;
    const __half* cp = g_coup + (size_t)s * K_N * 128 + tid;
#pragma unroll 2
    for (int k = 0; k < K_N; ++k)
        a = fmaf(sAtt[k], __half2float(cp[k * 128]), a);
    out_combined[(size_t)s * 128 + tid] = a;
    if (tid < K_N)
        out_att[(size_t)s * K_N + tid] = sAtt[tid];
}

// ---------------- host launcher ----------------
extern "C" void kernel_launch(void* const* d_in, const int* in_sizes, int n_in,
                              void* d_out, int out_size) {
    const float* u_embs = (const float*)d_in[1];
    const float* i_embs = (const float*)d_in[3];
    const float* act    = (const float*)d_in[4];   // int32 data
    const float* table  = (const float*)d_in[5];
    const float* prof   = (const float*)d_in[6];
    const float* w_fus  = (const float*)d_in[7];
    const float* b_fus  = (const float*)d_in[8];
    const float* w_c1   = (const float*)d_in[9];
    const float* b_c1   = (const float*)d_in[10];
    const float* w_c2   = (const float*)d_in[11];
    const float* b_c2   = (const float*)d_in[12];
    const float* w_a1   = (const float*)d_in[13];
    const float* b_a1   = (const float*)d_in[14];
    const float* w_a2   = (const float*)d_in[15];
    const float* b_a2   = (const float*)d_in[16];
    const float* w_a3   = (const float*)d_in[17];
    const float* b_a3   = (const float*)d_in[18];

    int B = in_sizes[0];   // 4096

    float* out_combined = (float*)d_out;
    float* out_att      = out_combined + (size_t)B * 128;

    int vblocks = ((B + 7) / 8) * 2;
    prep_all<<<96 + vblocks, 256>>>(w_fus, w_c1, w_c2, w_a1, w_a2,
                                    i_embs, u_embs, b_c1, b_a1, B);

    int G = B * K_N;
    int grid = (G + 127) / 128;            // 1600 for B=4096 (exact)
    cudaFuncSetAttribute(influence_main,
                         cudaFuncAttributeMaxDynamicSharedMemorySize, SM_TOTAL);
    influence_main<<<grid, 256, SM_TOTAL>>>(
        act, table, prof,
        b_fus, b_c2, b_a2, w_a3, b_a3, B);

    influence_finish<<<B, 128>>>(out_combined, out_att);
}

// round 15
// speedup vs baseline: 1.0560x; 1.0560x over previous
#include <cuda_runtime.h>
#include <cuda_fp16.h>
#include <cstdint>

// InfluenceProp R15: R14 (fp16 coup) with prep_all reverted to R13 geometry
// (vec blocks = 16 samples for full W reuse; weight blocks = 48x2048).

#define K_N 50

// ---------------- gmem scratch ----------------
__device__ __align__(1024) __half g_wb[6 * 16384];   // 6 units x 128x128 fp16
__device__ float g_vec[2ull * 4096 * 128];           // folded biases [which][b][128]
__device__ __half g_coup[204800ull * 128];           // coup fp16 per global row
__device__ float g_score[204928];                    // raw scores per global row

// ---------------- smem byte offsets ----------------
#define SM_A     0          // 128x128 fp16 swizzled (32KB)
#define SM_B0    32768      // 128x128 fp16 (32KB)
#define SM_B1    65536
#define SM_IDX   98304      // 128 ints
#define SM_BFUS  98816
#define SM_BC2   99328
#define SM_BA2   99840
#define SM_W3    100352
#define SM_VC1   100864     // [4][128] f
#define SM_VA1   102912     // [4][128] f
#define SM_TOTAL 104960

// tile layout: row r, 256 B/row; 16B chunk c stored at (c ^ (r&7))
__device__ __host__ __forceinline__ int tile_off(int r, int c) {
    return r * 256 + ((c ^ (r & 7)) << 4);
}

__device__ __forceinline__ uint32_t smem_u32(const void* p) {
    uint32_t a;
    asm("{ .reg .u64 t; cvta.to.shared.u64 t, %1; cvt.u32.u64 %0, t; }" : "=r"(a) : "l"(p));
    return a;
}

#define LDSM4(r0, r1, r2, r3, addr) \
    asm volatile("ldmatrix.sync.aligned.m8n8.x4.shared.b16 {%0,%1,%2,%3}, [%4];" \
                 : "=r"(r0), "=r"(r1), "=r"(r2), "=r"(r3) : "r"(addr))
#define MMA(ac, a0, a1, a2, a3, b0, b1) \
    asm volatile("mma.sync.aligned.m16n8k16.row.col.f32.f16.f16.f32 " \
                 "{%0,%1,%2,%3},{%4,%5,%6,%7},{%8,%9},{%0,%1,%2,%3};" \
                 : "+f"((ac)[0]), "+f"((ac)[1]), "+f"((ac)[2]), "+f"((ac)[3]) \
                 : "r"(a0), "r"(a1), "r"(a2), "r"(a3), "r"(b0), "r"(b1))

__device__ __forceinline__ uint32_t pkf2(float a, float b) {
    __half2 t = __floats2half2_rn(a, b);
    uint32_t u; __builtin_memcpy(&u, &t, 4);
    return u;
}

// ---------------- fused prepass: weights + folded bias vectors ----------------
__global__ void prep_all(
    const float* __restrict__ w_fus, const float* __restrict__ w_c1,
    const float* __restrict__ w_c2,  const float* __restrict__ w_a1,
    const float* __restrict__ w_a2,
    const float* __restrict__ i_embs, const float* __restrict__ u_embs,
    const float* __restrict__ b_c1,   const float* __restrict__ b_a1,
    int Btot)
{
    int bid = blockIdx.x;
    int tid = threadIdx.x;
    if (bid < 48) {
        // weight fp16 + transpose + swizzle
        int u = bid >> 3;
        int part = bid & 7;
        const float* base; int koff = 0;
        if      (u == 0) { base = w_fus; }
        else if (u == 1) { base = w_fus; koff = 128; }
        else if (u == 2) { base = w_c1; }
        else if (u == 3) { base = w_c2; }
        else if (u == 4) { base = w_a1; }
        else             { base = w_a2; }
        int e0 = part * 2048;
        for (int i = tid; i < 2048; i += blockDim.x) {
            int e = e0 + i;
            int n = e >> 7, k = e & 127;
            float v = base[(size_t)(k + koff) * 128 + n];
            int elem = (n * 256 + (((k >> 3) ^ (n & 7)) << 4) + (k & 7) * 2) >> 1;
            g_wb[(size_t)u * 16384 + elem] = __float2half_rn(v);
        }
        return;
    }
    // folded bias vectors: 16 samples per block (full W reuse)
    __shared__ float sE[16 * 128];
    __shared__ float sW[32 * 128];
    int v = bid - 48;
    int which = v & 1;
    int bbase = (v >> 1) * 16;
    const float* emb = which ? u_embs : i_embs;
    const float* W   = (which ? w_a1 : w_c1) + (size_t)128 * 128;
    const float* bb  = which ? b_a1 : b_c1;

    for (int idx = tid; idx < 2048; idx += 256) {
        int s = idx >> 7, c = idx & 127;
        sE[idx] = (bbase + s < Btot) ? emb[(size_t)(bbase + s) * 128 + c] : 0.f;
    }
    int col = tid & 127;
    int sg  = tid >> 7;                 // samples sg*8 .. sg*8+7
    float acc[8];
#pragma unroll
    for (int j = 0; j < 8; ++j) acc[j] = bb[col];

    for (int kc = 0; kc < 4; ++kc) {
        __syncthreads();
        for (int idx = tid; idx < 4096; idx += 256)
            sW[idx] = W[(size_t)(kc * 32 + (idx >> 7)) * 128 + (idx & 127)];
        __syncthreads();
#pragma unroll 8
        for (int kk = 0; kk < 32; ++kk) {
            float w = sW[kk * 128 + col];
#pragma unroll
            for (int j = 0; j < 8; ++j)
                acc[j] = fmaf(sE[(sg * 8 + j) * 128 + kc * 32 + kk], w, acc[j]);
        }
    }
#pragma unroll
    for (int j = 0; j < 8; ++j) {
        int s = bbase + sg * 8 + j;
        if (s < Btot)
            g_vec[(size_t)which * Btot * 128 + (size_t)s * 128 + col] = acc[j];
    }
}

// ---------------- main kernel pieces ----------------
__device__ __forceinline__ void copy_unit(int u, uint32_t dstAddr, int tid) {
    const char* src = (const char*)g_wb + (size_t)u * 32768;
#pragma unroll
    for (int t = 0; t < 8; ++t) {
        int i = tid + t * 256;             // 0..2047 16B lines
        asm volatile("cp.async.cg.shared.global [%0], [%1], 16;"
                     :: "r"(dstAddr + i * 16), "l"(src + (size_t)i * 16));
    }
    asm volatile("cp.async.commit_group;" ::: "memory");
}

// single-term sweep over K=128: warp w owns rows [16w,16w+16) x full N=128.
__device__ __forceinline__ void sweep(
    float (&acc)[16][4],
    uint32_t aT, uint32_t bB,
    int w, int l)
{
    const int rA = 16 * w + (l & 15);
    const uint32_t aRowOff = (uint32_t)rA * 256;
    const int axor = rA & 7;
    const int khA = l >> 4;
    const uint32_t bLane = (uint32_t)(((l >> 4) & 1) * 2048 + (l & 7) * 256);
    const int bKh  = (l >> 3) & 1;
    const int bxor = l & 7;

#pragma unroll 1
    for (int ks = 0; ks < 8; ++ks) {
        uint32_t aoff = aRowOff + (uint32_t)(((2 * ks + khA) ^ axor) << 4);
        uint32_t a0, a1, a2, a3;
        LDSM4(a0, a1, a2, a3, aT + aoff);

        uint32_t bko = bLane + (uint32_t)(((2 * ks + bKh) ^ bxor) << 4);

        uint32_t bh[8][2];
#pragma unroll
        for (int p = 0; p < 4; ++p)
            LDSM4(bh[2 * p][0], bh[2 * p][1], bh[2 * p + 1][0], bh[2 * p + 1][1],
                  bB + (uint32_t)p * 4096 + bko);
#pragma unroll
        for (int t = 0; t < 8; ++t)
            MMA(acc[t], a0, a1, a2, a3, bh[t][0], bh[t][1]);
#pragma unroll
        for (int p = 0; p < 4; ++p)
            LDSM4(bh[2 * p][0], bh[2 * p][1], bh[2 * p + 1][0], bh[2 * p + 1][1],
                  bB + (uint32_t)(p + 4) * 4096 + bko);
#pragma unroll
        for (int t = 0; t < 8; ++t)
            MMA(acc[t + 8], a0, a1, a2, a3, bh[t][0], bh[t][1]);
    }
}

// gather table rows -> fp16 -> swizzled A tile (all 128 local rows valid)
__device__ __forceinline__ void gatherA(
    const float* __restrict__ tbl, const int* sIdx, char* smemc, int tid)
{
    for (int idx = tid; idx < 2048; idx += 256) {
        int r = idx >> 4;
        int c = idx & 15;
        int u = sIdx[r];
        const float4* src = (const float4*)(tbl + (size_t)u * 128 + c * 8);
        float4 v0 = src[0], v1 = src[1];
        uint4 hv = make_uint4(pkf2(v0.x, v0.y), pkf2(v0.z, v0.w),
                              pkf2(v1.x, v1.y), pkf2(v1.z, v1.w));
        *(uint4*)(smemc + SM_A + tile_off(r, c)) = hv;
    }
}

// bias + relu -> fp16 back into A tile (opt: fp16 coup to gmem); resets acc.
__device__ __forceinline__ void epilogueA(
    float (&acc)[16][4], char* smemc,
    const float* vec, int vstride,
    int gBase, int s_first,
    bool writeCoup, int w, int l)
{
    int q  = 16 * w + (l >> 2);
    int p2 = (l & 3) * 2;
    int r0 = q, r1 = q + 8;
    int s0 = (gBase + r0) / K_N - s_first;
    int s1 = (gBase + r1) / K_N - s_first;
    const float* bv0 = vec + s0 * vstride;
    const float* bv1 = vec + s1 * vstride;
    uint32_t* coup32 = (uint32_t*)g_coup;
#pragma unroll
    for (int t = 0; t < 16; ++t) {
        int n = 8 * t + p2;
        float y00 = fmaxf(acc[t][0] + bv0[n],     0.f);
        float y01 = fmaxf(acc[t][1] + bv0[n + 1], 0.f);
        float y10 = fmaxf(acc[t][2] + bv1[n],     0.f);
        float y11 = fmaxf(acc[t][3] + bv1[n + 1], 0.f);
        acc[t][0] = 0.f; acc[t][1] = 0.f; acc[t][2] = 0.f; acc[t][3] = 0.f;
        uint32_t h0 = pkf2(y00, y01);
        uint32_t h1 = pkf2(y10, y11);
        *(uint32_t*)(smemc + SM_A + tile_off(r0, t) + p2 * 2) = h0;
        *(uint32_t*)(smemc + SM_A + tile_off(r1, t) + p2 * 2) = h1;
        if (writeCoup) {
            coup32[(size_t)(gBase + r0) * 64 + (n >> 1)] = h0;
            coup32[(size_t)(gBase + r1) * 64 + (n >> 1)] = h1;
        }
    }
}

// last layer: bias+relu (shared ba2), dot w3, quad reduce -> g_score[global row]
__device__ __forceinline__ void epilogueScore(
    float (&acc)[16][4], const float* ba2, const float* w3, float b3,
    int gBase, int w, int l)
{
    int q  = 16 * w + (l >> 2);
    int p2 = (l & 3) * 2;
    float p0 = 0.f, p1 = 0.f;
#pragma unroll
    for (int t = 0; t < 16; ++t) {
        int n = 8 * t + p2;
        p0 = fmaf(fmaxf(acc[t][0] + ba2[n],     0.f), w3[n],     p0);
        p0 = fmaf(fmaxf(acc[t][1] + ba2[n + 1], 0.f), w3[n + 1], p0);
        p1 = fmaf(fmaxf(acc[t][2] + ba2[n],     0.f), w3[n],     p1);
        p1 = fmaf(fmaxf(acc[t][3] + ba2[n + 1], 0.f), w3[n + 1], p1);
    }
    p0 += __shfl_xor_sync(0xffffffffu, p0, 1);
    p0 += __shfl_xor_sync(0xffffffffu, p0, 2);
    p1 += __shfl_xor_sync(0xffffffffu, p1, 1);
    p1 += __shfl_xor_sync(0xffffffffu, p1, 2);
    if ((l & 3) == 0) {
        g_score[gBase + q]     = p0 + b3;
        g_score[gBase + q + 8] = p1 + b3;
    }
}

#define WAITG(n) asm volatile("cp.async.wait_group %0;" :: "n"(n) : "memory")

__global__ __launch_bounds__(256, 2)
void influence_main(
    const float* __restrict__ act_users_f,
    const float* __restrict__ emb_table, const float* __restrict__ prof_table,
    const float* __restrict__ b_fus, const float* __restrict__ b_c2,
    const float* __restrict__ b_a2,  const float* __restrict__ w_a3,
    const float* __restrict__ b_a3,
    int Btot)
{
    extern __shared__ char smemc[];
    const int tid = threadIdx.x;
    const int w = tid >> 5, l = tid & 31;
    const int gBase = blockIdx.x * 128;
    const int G = Btot * K_N;
    const int s_first = gBase / K_N;
    const int* act_users = (const int*)act_users_f;   // flat [B*50]
    uint32_t sb = smem_u32(smemc);

    int* sIdx     = (int*)(smemc + SM_IDX);
    float* sBfus  = (float*)(smemc + SM_BFUS);
    float* sBc2   = (float*)(smemc + SM_BC2);
    float* sBa2   = (float*)(smemc + SM_BA2);
    float* sW3    = (float*)(smemc + SM_W3);
    float* sVC1   = (float*)(smemc + SM_VC1);
    float* sVA1   = (float*)(smemc + SM_VA1);

    copy_unit(0, sb + SM_B0, tid);
    copy_unit(1, sb + SM_B1, tid);

    if (tid < 128) {
        int g = gBase + tid;
        sIdx[tid] = (g < G) ? act_users[g] : 0;
    } else {
        int c = tid - 128;
        sBfus[c] = b_fus[c];
        sBc2[c]  = b_c2[c];
        sBa2[c]  = b_a2[c];
        sW3[c]   = w_a3[c];
    }
    // stage up to 4 per-sample folded bias vectors
    for (int idx = tid; idx < 4 * 128; idx += 256) {
        int j = idx >> 7, c = idx & 127;
        int s = s_first + j; if (s > Btot - 1) s = Btot - 1;
        sVC1[idx] = g_vec[(size_t)s * 128 + c];
        sVA1[idx] = g_vec[(size_t)Btot * 128 + (size_t)s * 128 + c];
    }
    __syncthreads();                       // sIdx visible
    gatherA(emb_table, sIdx, smemc, tid);

    float acc[16][4];
#pragma unroll
    for (int t = 0; t < 16; ++t) {
        acc[t][0] = 0.f; acc[t][1] = 0.f; acc[t][2] = 0.f; acc[t][3] = 0.f;
    }

    WAITG(1); __syncthreads();             // A(emb) + unit0 ready
    sweep(acc, sb + SM_A, sb + SM_B0, w, l);
    __syncthreads();                       // B0 free, A free
    copy_unit(2, sb + SM_B0, tid);
    gatherA(prof_table, sIdx, smemc, tid);
    WAITG(1); __syncthreads();             // A(prof) + unit1 ready
    sweep(acc, sb + SM_A, sb + SM_B1, w, l);
    __syncthreads();                       // B1 free, A free
    copy_unit(3, sb + SM_B1, tid);
    epilogueA(acc, smemc, sBfus, 0, gBase, s_first, false, w, l);   // L1
    WAITG(1); __syncthreads();
    sweep(acc, sb + SM_A, sb + SM_B0, w, l);                        // L2
    __syncthreads();
    copy_unit(4, sb + SM_B0, tid);
    epilogueA(acc, smemc, sVC1, 128, gBase, s_first, false, w, l);  // L2 -> c1
    WAITG(1); __syncthreads();
    sweep(acc, sb + SM_A, sb + SM_B1, w, l);                        // L3
    __syncthreads();
    copy_unit(5, sb + SM_B1, tid);
    epilogueA(acc, smemc, sBc2, 0, gBase, s_first, true, w, l);     // L3 -> coup
    WAITG(1); __syncthreads();
    sweep(acc, sb + SM_A, sb + SM_B0, w, l);                        // L4
    __syncthreads();
    epilogueA(acc, smemc, sVA1, 128, gBase, s_first, false, w, l);  // L4 -> h
    WAITG(0); __syncthreads();
    sweep(acc, sb + SM_A, sb + SM_B1, w, l);                        // L5
    epilogueScore(acc, sBa2, sW3, b_a3[0], gBase, w, l);
}

// ---------------- finish: per-sample softmax + aggregation ----------------
__global__ __launch_bounds__(128)
void influence_finish(
    float* __restrict__ out_combined, float* __restrict__ out_att)
{
    __shared__ float sAtt[64];
    int s = blockIdx.x;
    int tid = threadIdx.x;
    int l = tid & 31;

    if (tid < 32) {
        float v1 = (l < K_N)      ? g_score[s * K_N + l]      : -1e30f;
        float v2 = (l + 32 < K_N) ? g_score[s * K_N + l + 32] : -1e30f;
        float m = fmaxf(v1, v2);
#pragma unroll
        for (int o = 16; o; o >>= 1)
            m = fmaxf(m, __shfl_xor_sync(0xffffffffu, m, o));
        float e1 = (l < K_N)      ? expf(v1 - m) : 0.f;
        float e2 = (l + 32 < K_N) ? expf(v2 - m) : 0.f;
        float sum = e1 + e2;
#pragma unroll
        for (int o = 16; o; o >>= 1)
            sum += __shfl_xor_sync(0xffffffffu, sum, o);
        float inv = 1.f / sum;
        if (l < K_N)      sAtt[l]      = e1 * inv;
        if (l + 32 < K_N) sAtt[l + 32] = e2 * inv;
    }
    __syncthreads();

    float a = 0.f;
    const __half* cp = g_coup + (size_t)s * K_N * 128 + tid;
#pragma unroll 2
    for (int k = 0; k < K_N; ++k)
        a = fmaf(sAtt[k], __half2float(cp[k * 128]), a);
    out_combined[(size_t)s * 128 + tid] = a;
    if (tid < K_N)
        out_att[(size_t)s * K_N + tid] = sAtt[tid];
}

// ---------------- host launcher ----------------
extern "C" void kernel_launch(void* const* d_in, const int* in_sizes, int n_in,
                              void* d_out, int out_size) {
    const float* u_embs = (const float*)d_in[1];
    const float* i_embs = (const float*)d_in[3];
    const float* act    = (const float*)d_in[4];   // int32 data
    const float* table  = (const float*)d_in[5];
    const float* prof   = (const float*)d_in[6];
    const float* w_fus  = (const float*)d_in[7];
    const float* b_fus  = (const float*)d_in[8];
    const float* w_c1   = (const float*)d_in[9];
    const float* b_c1   = (const float*)d_in[10];
    const float* w_c2   = (const float*)d_in[11];
    const float* b_c2   = (const float*)d_in[12];
    const float* w_a1   = (const float*)d_in[13];
    const float* b_a1   = (const float*)d_in[14];
    const float* w_a2   = (const float*)d_in[15];
    const float* b_a2   = (const float*)d_in[16];
    const float* w_a3   = (const float*)d_in[17];
    const float* b_a3   = (const float*)d_in[18];

    int B = in_sizes[0];   // 4096

    float* out_combined = (float*)d_out;
    float* out_att      = out_combined + (size_t)B * 128;

    int vblocks = ((B + 15) / 16) * 2;
    prep_all<<<48 + vblocks, 256>>>(w_fus, w_c1, w_c2, w_a1, w_a2,
                                    i_embs, u_embs, b_c1, b_a1, B);

    int G = B * K_N;
    int grid = (G + 127) / 128;            // 1600 for B=4096 (exact)
    cudaFuncSetAttribute(influence_main,
                         cudaFuncAttributeMaxDynamicSharedMemorySize, SM_TOTAL);
    influence_main<<<grid, 256, SM_TOTAL>>>(
        act, table, prof,
        b_fus, b_c2, b_a2, w_a3, b_a3, B);

    influence_finish<<<B, 128>>>(out_combined, out_att);
}

// round 16
// speedup vs baseline: 1.0593x; 1.0031x over previous
#include <cuda_runtime.h>
#include <cuda_fp16.h>
#include <cstdint>

// InfluenceProp R16: R15 main kernel unchanged. prep_all vec blocks upgraded
// to 512 threads / 32 samples (W reuse x2, staged loads unrolled for MLP);
// finish processes 2 samples per block.

#define K_N 50

// ---------------- gmem scratch ----------------
__device__ __align__(1024) __half g_wb[6 * 16384];   // 6 units x 128x128 fp16
__device__ float g_vec[2ull * 4096 * 128];           // folded biases [which][b][128]
__device__ __half g_coup[204800ull * 128];           // coup fp16 per global row
__device__ float g_score[204928];                    // raw scores per global row

// ---------------- smem byte offsets (main) ----------------
#define SM_A     0          // 128x128 fp16 swizzled (32KB)
#define SM_B0    32768      // 128x128 fp16 (32KB)
#define SM_B1    65536
#define SM_IDX   98304      // 128 ints
#define SM_BFUS  98816
#define SM_BC2   99328
#define SM_BA2   99840
#define SM_W3    100352
#define SM_VC1   100864     // [4][128] f
#define SM_VA1   102912     // [4][128] f
#define SM_TOTAL 104960

// tile layout: row r, 256 B/row; 16B chunk c stored at (c ^ (r&7))
__device__ __host__ __forceinline__ int tile_off(int r, int c) {
    return r * 256 + ((c ^ (r & 7)) << 4);
}

__device__ __forceinline__ uint32_t smem_u32(const void* p) {
    uint32_t a;
    asm("{ .reg .u64 t; cvta.to.shared.u64 t, %1; cvt.u32.u64 %0, t; }" : "=r"(a) : "l"(p));
    return a;
}

#define LDSM4(r0, r1, r2, r3, addr) \
    asm volatile("ldmatrix.sync.aligned.m8n8.x4.shared.b16 {%0,%1,%2,%3}, [%4];" \
                 : "=r"(r0), "=r"(r1), "=r"(r2), "=r"(r3) : "r"(addr))
#define MMA(ac, a0, a1, a2, a3, b0, b1) \
    asm volatile("mma.sync.aligned.m16n8k16.row.col.f32.f16.f16.f32 " \
                 "{%0,%1,%2,%3},{%4,%5,%6,%7},{%8,%9},{%0,%1,%2,%3};" \
                 : "+f"((ac)[0]), "+f"((ac)[1]), "+f"((ac)[2]), "+f"((ac)[3]) \
                 : "r"(a0), "r"(a1), "r"(a2), "r"(a3), "r"(b0), "r"(b1))

__device__ __forceinline__ uint32_t pkf2(float a, float b) {
    __half2 t = __floats2half2_rn(a, b);
    uint32_t u; __builtin_memcpy(&u, &t, 4);
    return u;
}

// ---------------- prepass A: weight fp16 + transpose + swizzle ----------------
__global__ void prep_w(
    const float* __restrict__ w_fus, const float* __restrict__ w_c1,
    const float* __restrict__ w_c2,  const float* __restrict__ w_a1,
    const float* __restrict__ w_a2)
{
    int bid = blockIdx.x;
    int tid = threadIdx.x;
    int u = bid >> 3;
    int part = bid & 7;
    const float* base; int koff = 0;
    if      (u == 0) { base = w_fus; }
    else if (u == 1) { base = w_fus; koff = 128; }
    else if (u == 2) { base = w_c1; }
    else if (u == 3) { base = w_c2; }
    else if (u == 4) { base = w_a1; }
    else             { base = w_a2; }
    int e0 = part * 2048;
#pragma unroll 4
    for (int i = tid; i < 2048; i += 256) {
        int e = e0 + i;
        int n = e >> 7, k = e & 127;
        float v = base[(size_t)(k + koff) * 128 + n];
        int elem = (n * 256 + (((k >> 3) ^ (n & 7)) << 4) + (k & 7) * 2) >> 1;
        g_wb[(size_t)u * 16384 + elem] = __float2half_rn(v);
    }
}

// ---------------- prepass B: folded bias vectors, 32 samples/block ----------------
__global__ __launch_bounds__(512)
void prep_vecs(
    const float* __restrict__ i_embs, const float* __restrict__ u_embs,
    const float* __restrict__ w_c1,   const float* __restrict__ b_c1,
    const float* __restrict__ w_a1,   const float* __restrict__ b_a1,
    int Btot)
{
    __shared__ float sE[32 * 128];
    __shared__ float sW[32 * 128];
    int which = blockIdx.x & 1;
    int bbase = (blockIdx.x >> 1) * 32;
    const float* emb = which ? u_embs : i_embs;
    const float* W   = (which ? w_a1 : w_c1) + (size_t)128 * 128;
    const float* bb  = which ? b_a1 : b_c1;
    int tid = threadIdx.x;

#pragma unroll 4
    for (int idx = tid; idx < 4096; idx += 512) {
        int s = idx >> 7, c = idx & 127;
        sE[idx] = (bbase + s < Btot) ? emb[(size_t)(bbase + s) * 128 + c] : 0.f;
    }
    int col = tid & 127;
    int sg  = tid >> 7;                 // samples sg*8 .. sg*8+7
    float acc[8];
#pragma unroll
    for (int j = 0; j < 8; ++j) acc[j] = bb[col];

    for (int kc = 0; kc < 4; ++kc) {
        __syncthreads();
#pragma unroll 4
        for (int idx = tid; idx < 4096; idx += 512)
            sW[idx] = W[(size_t)(kc * 32 + (idx >> 7)) * 128 + (idx & 127)];
        __syncthreads();
#pragma unroll 8
        for (int kk = 0; kk < 32; ++kk) {
            float w = sW[kk * 128 + col];
#pragma unroll
            for (int j = 0; j < 8; ++j)
                acc[j] = fmaf(sE[(sg * 8 + j) * 128 + kc * 32 + kk], w, acc[j]);
        }
    }
#pragma unroll
    for (int j = 0; j < 8; ++j) {
        int s = bbase + sg * 8 + j;
        if (s < Btot)
            g_vec[(size_t)which * Btot * 128 + (size_t)s * 128 + col] = acc[j];
    }
}

// ---------------- main kernel pieces (unchanged from R15) ----------------
__device__ __forceinline__ void copy_unit(int u, uint32_t dstAddr, int tid) {
    const char* src = (const char*)g_wb + (size_t)u * 32768;
#pragma unroll
    for (int t = 0; t < 8; ++t) {
        int i = tid + t * 256;
        asm volatile("cp.async.cg.shared.global [%0], [%1], 16;"
                     :: "r"(dstAddr + i * 16), "l"(src + (size_t)i * 16));
    }
    asm volatile("cp.async.commit_group;" ::: "memory");
}

__device__ __forceinline__ void sweep(
    float (&acc)[16][4],
    uint32_t aT, uint32_t bB,
    int w, int l)
{
    const int rA = 16 * w + (l & 15);
    const uint32_t aRowOff = (uint32_t)rA * 256;
    const int axor = rA & 7;
    const int khA = l >> 4;
    const uint32_t bLane = (uint32_t)(((l >> 4) & 1) * 2048 + (l & 7) * 256);
    const int bKh  = (l >> 3) & 1;
    const int bxor = l & 7;

#pragma unroll 1
    for (int ks = 0; ks < 8; ++ks) {
        uint32_t aoff = aRowOff + (uint32_t)(((2 * ks + khA) ^ axor) << 4);
        uint32_t a0, a1, a2, a3;
        LDSM4(a0, a1, a2, a3, aT + aoff);

        uint32_t bko = bLane + (uint32_t)(((2 * ks + bKh) ^ bxor) << 4);

        uint32_t bh[8][2];
#pragma unroll
        for (int p = 0; p < 4; ++p)
            LDSM4(bh[2 * p][0], bh[2 * p][1], bh[2 * p + 1][0], bh[2 * p + 1][1],
                  bB + (uint32_t)p * 4096 + bko);
#pragma unroll
        for (int t = 0; t < 8; ++t)
            MMA(acc[t], a0, a1, a2, a3, bh[t][0], bh[t][1]);
#pragma unroll
        for (int p = 0; p < 4; ++p)
            LDSM4(bh[2 * p][0], bh[2 * p][1], bh[2 * p + 1][0], bh[2 * p + 1][1],
                  bB + (uint32_t)(p + 4) * 4096 + bko);
#pragma unroll
        for (int t = 0; t < 8; ++t)
            MMA(acc[t + 8], a0, a1, a2, a3, bh[t][0], bh[t][1]);
    }
}

__device__ __forceinline__ void gatherA(
    const float* __restrict__ tbl, const int* sIdx, char* smemc, int tid)
{
    for (int idx = tid; idx < 2048; idx += 256) {
        int r = idx >> 4;
        int c = idx & 15;
        int u = sIdx[r];
        const float4* src = (const float4*)(tbl + (size_t)u * 128 + c * 8);
        float4 v0 = src[0], v1 = src[1];
        uint4 hv = make_uint4(pkf2(v0.x, v0.y), pkf2(v0.z, v0.w),
                              pkf2(v1.x, v1.y), pkf2(v1.z, v1.w));
        *(uint4*)(smemc + SM_A + tile_off(r, c)) = hv;
    }
}

__device__ __forceinline__ void epilogueA(
    float (&acc)[16][4], char* smemc,
    const float* vec, int vstride,
    int gBase, int s_first,
    bool writeCoup, int w, int l)
{
    int q  = 16 * w + (l >> 2);
    int p2 = (l & 3) * 2;
    int r0 = q, r1 = q + 8;
    int s0 = (gBase + r0) / K_N - s_first;
    int s1 = (gBase + r1) / K_N - s_first;
    const float* bv0 = vec + s0 * vstride;
    const float* bv1 = vec + s1 * vstride;
    uint32_t* coup32 = (uint32_t*)g_coup;
#pragma unroll
    for (int t = 0; t < 16; ++t) {
        int n = 8 * t + p2;
        float y00 = fmaxf(acc[t][0] + bv0[n],     0.f);
        float y01 = fmaxf(acc[t][1] + bv0[n + 1], 0.f);
        float y10 = fmaxf(acc[t][2] + bv1[n],     0.f);
        float y11 = fmaxf(acc[t][3] + bv1[n + 1], 0.f);
        acc[t][0] = 0.f; acc[t][1] = 0.f; acc[t][2] = 0.f; acc[t][3] = 0.f;
        uint32_t h0 = pkf2(y00, y01);
        uint32_t h1 = pkf2(y10, y11);
        *(uint32_t*)(smemc + SM_A + tile_off(r0, t) + p2 * 2) = h0;
        *(uint32_t*)(smemc + SM_A + tile_off(r1, t) + p2 * 2) = h1;
        if (writeCoup) {
            coup32[(size_t)(gBase + r0) * 64 + (n >> 1)] = h0;
            coup32[(size_t)(gBase + r1) * 64 + (n >> 1)] = h1;
        }
    }
}

__device__ __forceinline__ void epilogueScore(
    float (&acc)[16][4], const float* ba2, const float* w3, float b3,
    int gBase, int w, int l)
{
    int q  = 16 * w + (l >> 2);
    int p2 = (l & 3) * 2;
    float p0 = 0.f, p1 = 0.f;
#pragma unroll
    for (int t = 0; t < 16; ++t) {
        int n = 8 * t + p2;
        p0 = fmaf(fmaxf(acc[t][0] + ba2[n],     0.f), w3[n],     p0);
        p0 = fmaf(fmaxf(acc[t][1] + ba2[n + 1], 0.f), w3[n + 1], p0);
        p1 = fmaf(fmaxf(acc[t][2] + ba2[n],     0.f), w3[n],     p1);
        p1 = fmaf(fmaxf(acc[t][3] + ba2[n + 1], 0.f), w3[n + 1], p1);
    }
    p0 += __shfl_xor_sync(0xffffffffu, p0, 1);
    p0 += __shfl_xor_sync(0xffffffffu, p0, 2);
    p1 += __shfl_xor_sync(0xffffffffu, p1, 1);
    p1 += __shfl_xor_sync(0xffffffffu, p1, 2);
    if ((l & 3) == 0) {
        g_score[gBase + q]     = p0 + b3;
        g_score[gBase + q + 8] = p1 + b3;
    }
}

#define WAITG(n) asm volatile("cp.async.wait_group %0;" :: "n"(n) : "memory")

__global__ __launch_bounds__(256, 2)
void influence_main(
    const float* __restrict__ act_users_f,
    const float* __restrict__ emb_table, const float* __restrict__ prof_table,
    const float* __restrict__ b_fus, const float* __restrict__ b_c2,
    const float* __restrict__ b_a2,  const float* __restrict__ w_a3,
    const float* __restrict__ b_a3,
    int Btot)
{
    extern __shared__ char smemc[];
    const int tid = threadIdx.x;
    const int w = tid >> 5, l = tid & 31;
    const int gBase = blockIdx.x * 128;
    const int G = Btot * K_N;
    const int s_first = gBase / K_N;
    const int* act_users = (const int*)act_users_f;
    uint32_t sb = smem_u32(smemc);

    int* sIdx     = (int*)(smemc + SM_IDX);
    float* sBfus  = (float*)(smemc + SM_BFUS);
    float* sBc2   = (float*)(smemc + SM_BC2);
    float* sBa2   = (float*)(smemc + SM_BA2);
    float* sW3    = (float*)(smemc + SM_W3);
    float* sVC1   = (float*)(smemc + SM_VC1);
    float* sVA1   = (float*)(smemc + SM_VA1);

    copy_unit(0, sb + SM_B0, tid);
    copy_unit(1, sb + SM_B1, tid);

    if (tid < 128) {
        int g = gBase + tid;
        sIdx[tid] = (g < G) ? act_users[g] : 0;
    } else {
        int c = tid - 128;
        sBfus[c] = b_fus[c];
        sBc2[c]  = b_c2[c];
        sBa2[c]  = b_a2[c];
        sW3[c]   = w_a3[c];
    }
    for (int idx = tid; idx < 4 * 128; idx += 256) {
        int j = idx >> 7, c = idx & 127;
        int s = s_first + j; if (s > Btot - 1) s = Btot - 1;
        sVC1[idx] = g_vec[(size_t)s * 128 + c];
        sVA1[idx] = g_vec[(size_t)Btot * 128 + (size_t)s * 128 + c];
    }
    __syncthreads();
    gatherA(emb_table, sIdx, smemc, tid);

    float acc[16][4];
#pragma unroll
    for (int t = 0; t < 16; ++t) {
        acc[t][0] = 0.f; acc[t][1] = 0.f; acc[t][2] = 0.f; acc[t][3] = 0.f;
    }

    WAITG(1); __syncthreads();
    sweep(acc, sb + SM_A, sb + SM_B0, w, l);
    __syncthreads();
    copy_unit(2, sb + SM_B0, tid);
    gatherA(prof_table, sIdx, smemc, tid);
    WAITG(1); __syncthreads();
    sweep(acc, sb + SM_A, sb + SM_B1, w, l);
    __syncthreads();
    copy_unit(3, sb + SM_B1, tid);
    epilogueA(acc, smemc, sBfus, 0, gBase, s_first, false, w, l);   // L1
    WAITG(1); __syncthreads();
    sweep(acc, sb + SM_A, sb + SM_B0, w, l);                        // L2
    __syncthreads();
    copy_unit(4, sb + SM_B0, tid);
    epilogueA(acc, smemc, sVC1, 128, gBase, s_first, false, w, l);  // L2 -> c1
    WAITG(1); __syncthreads();
    sweep(acc, sb + SM_A, sb + SM_B1, w, l);                        // L3
    __syncthreads();
    copy_unit(5, sb + SM_B1, tid);
    epilogueA(acc, smemc, sBc2, 0, gBase, s_first, true, w, l);     // L3 -> coup
    WAITG(1); __syncthreads();
    sweep(acc, sb + SM_A, sb + SM_B0, w, l);                        // L4
    __syncthreads();
    epilogueA(acc, smemc, sVA1, 128, gBase, s_first, false, w, l);  // L4 -> h
    WAITG(0); __syncthreads();
    sweep(acc, sb + SM_A, sb + SM_B1, w, l);                        // L5
    epilogueScore(acc, sBa2, sW3, b_a3[0], gBase, w, l);
}

// ---------------- finish: softmax + aggregation, 2 samples/block ----------------
__global__ __launch_bounds__(256)
void influence_finish(
    float* __restrict__ out_combined, float* __restrict__ out_att)
{
    __shared__ float sAtt[2][64];
    int s0 = blockIdx.x * 2;
    int tid = threadIdx.x;
    int half = tid >> 7;                 // sample within block
    int ht = tid & 127;
    int s = s0 + half;
    int l = ht & 31;

    if (ht < 32) {
        float v1 = (l < K_N)      ? g_score[s * K_N + l]      : -1e30f;
        float v2 = (l + 32 < K_N) ? g_score[s * K_N + l + 32] : -1e30f;
        float m = fmaxf(v1, v2);
#pragma unroll
        for (int o = 16; o; o >>= 1)
            m = fmaxf(m, __shfl_xor_sync(0xffffffffu, m, o));
        float e1 = (l < K_N)      ? expf(v1 - m) : 0.f;
        float e2 = (l + 32 < K_N) ? expf(v2 - m) : 0.f;
        float sum = e1 + e2;
#pragma unroll
        for (int o = 16; o; o >>= 1)
            sum += __shfl_xor_sync(0xffffffffu, sum, o);
        float inv = 1.f / sum;
        if (l < K_N)      sAtt[half][l]      = e1 * inv;
        if (l + 32 < K_N) sAtt[half][l + 32] = e2 * inv;
    }
    __syncthreads();

    float a = 0.f;
    const __half* cp = g_coup + (size_t)s * K_N * 128 + ht;
#pragma unroll 2
    for (int k = 0; k < K_N; ++k)
        a = fmaf(sAtt[half][k], __half2float(cp[k * 128]), a);
    out_combined[(size_t)s * 128 + ht] = a;
    if (ht < K_N)
        out_att[(size_t)s * K_N + ht] = sAtt[half][ht];
}

// ---------------- host launcher ----------------
extern "C" void kernel_launch(void* const* d_in, const int* in_sizes, int n_in,
                              void* d_out, int out_size) {
    const float* u_embs = (const float*)d_in[1];
    const float* i_embs = (const float*)d_in[3];
    const float* act    = (const float*)d_in[4];   // int32 data
    const float* table  = (const float*)d_in[5];
    const float* prof   = (const float*)d_in[6];
    const float* w_fus  = (const float*)d_in[7];
    const float* b_fus  = (const float*)d_in[8];
    const float* w_c1   = (const float*)d_in[9];
    const float* b_c1   = (const float*)d_in[10];
    const float* w_c2   = (const float*)d_in[11];
    const float* b_c2   = (const float*)d_in[12];
    const float* w_a1   = (const float*)d_in[13];
    const float* b_a1   = (const float*)d_in[14];
    const float* w_a2   = (const float*)d_in[15];
    const float* b_a2   = (const float*)d_in[16];
    const float* w_a3   = (const float*)d_in[17];
    const float* b_a3   = (const float*)d_in[18];

    int B = in_sizes[0];   // 4096

    float* out_combined = (float*)d_out;
    float* out_att      = out_combined + (size_t)B * 128;

    prep_w<<<48, 256>>>(w_fus, w_c1, w_c2, w_a1, w_a2);
    prep_vecs<<<((B + 31) / 32) * 2, 512>>>(i_embs, u_embs,
                                            w_c1, b_c1, w_a1, b_a1, B);

    int G = B * K_N;
    int grid = (G + 127) / 128;            // 1600 for B=4096 (exact)
    cudaFuncSetAttribute(influence_main,
                         cudaFuncAttributeMaxDynamicSharedMemorySize, SM_TOTAL);
    influence_main<<<grid, 256, SM_TOTAL>>>(
        act, table, prof,
        b_fus, b_c2, b_a2, w_a3, b_a3, B);

    influence_finish<<<B / 2, 256>>>(out_combined, out_att);
}

// round 17
// speedup vs baseline: 1.1323x; 1.0689x over previous
#include <cuda_runtime.h>
#include <cuda_fp16.h>
#include <cstdint>

// InfluenceProp R17: R16 main + prepasses unchanged. Finish kernel rebuilt:
// full k-loop unroll (MLP 2 -> ~50) + half2 column-pair loads, 4 samples per
// 256-thread block. Same fp32 math order -> identical outputs.

#define K_N 50

// ---------------- gmem scratch ----------------
__device__ __align__(1024) __half g_wb[6 * 16384];   // 6 units x 128x128 fp16
__device__ float g_vec[2ull * 4096 * 128];           // folded biases [which][b][128]
__device__ __half g_coup[204800ull * 128];           // coup fp16 per global row
__device__ float g_score[204928];                    // raw scores per global row

// ---------------- smem byte offsets (main) ----------------
#define SM_A     0          // 128x128 fp16 swizzled (32KB)
#define SM_B0    32768      // 128x128 fp16 (32KB)
#define SM_B1    65536
#define SM_IDX   98304      // 128 ints
#define SM_BFUS  98816
#define SM_BC2   99328
#define SM_BA2   99840
#define SM_W3    100352
#define SM_VC1   100864     // [4][128] f
#define SM_VA1   102912     // [4][128] f
#define SM_TOTAL 104960

// tile layout: row r, 256 B/row; 16B chunk c stored at (c ^ (r&7))
__device__ __host__ __forceinline__ int tile_off(int r, int c) {
    return r * 256 + ((c ^ (r & 7)) << 4);
}

__device__ __forceinline__ uint32_t smem_u32(const void* p) {
    uint32_t a;
    asm("{ .reg .u64 t; cvta.to.shared.u64 t, %1; cvt.u32.u64 %0, t; }" : "=r"(a) : "l"(p));
    return a;
}

#define LDSM4(r0, r1, r2, r3, addr) \
    asm volatile("ldmatrix.sync.aligned.m8n8.x4.shared.b16 {%0,%1,%2,%3}, [%4];" \
                 : "=r"(r0), "=r"(r1), "=r"(r2), "=r"(r3) : "r"(addr))
#define MMA(ac, a0, a1, a2, a3, b0, b1) \
    asm volatile("mma.sync.aligned.m16n8k16.row.col.f32.f16.f16.f32 " \
                 "{%0,%1,%2,%3},{%4,%5,%6,%7},{%8,%9},{%0,%1,%2,%3};" \
                 : "+f"((ac)[0]), "+f"((ac)[1]), "+f"((ac)[2]), "+f"((ac)[3]) \
                 : "r"(a0), "r"(a1), "r"(a2), "r"(a3), "r"(b0), "r"(b1))

__device__ __forceinline__ uint32_t pkf2(float a, float b) {
    __half2 t = __floats2half2_rn(a, b);
    uint32_t u; __builtin_memcpy(&u, &t, 4);
    return u;
}

// ---------------- prepass A: weight fp16 + transpose + swizzle ----------------
__global__ void prep_w(
    const float* __restrict__ w_fus, const float* __restrict__ w_c1,
    const float* __restrict__ w_c2,  const float* __restrict__ w_a1,
    const float* __restrict__ w_a2)
{
    int bid = blockIdx.x;
    int tid = threadIdx.x;
    int u = bid >> 3;
    int part = bid & 7;
    const float* base; int koff = 0;
    if      (u == 0) { base = w_fus; }
    else if (u == 1) { base = w_fus; koff = 128; }
    else if (u == 2) { base = w_c1; }
    else if (u == 3) { base = w_c2; }
    else if (u == 4) { base = w_a1; }
    else             { base = w_a2; }
    int e0 = part * 2048;
#pragma unroll 4
    for (int i = tid; i < 2048; i += 256) {
        int e = e0 + i;
        int n = e >> 7, k = e & 127;
        float v = base[(size_t)(k + koff) * 128 + n];
        int elem = (n * 256 + (((k >> 3) ^ (n & 7)) << 4) + (k & 7) * 2) >> 1;
        g_wb[(size_t)u * 16384 + elem] = __float2half_rn(v);
    }
}

// ---------------- prepass B: folded bias vectors, 32 samples/block ----------------
__global__ __launch_bounds__(512)
void prep_vecs(
    const float* __restrict__ i_embs, const float* __restrict__ u_embs,
    const float* __restrict__ w_c1,   const float* __restrict__ b_c1,
    const float* __restrict__ w_a1,   const float* __restrict__ b_a1,
    int Btot)
{
    __shared__ float sE[32 * 128];
    __shared__ float sW[32 * 128];
    int which = blockIdx.x & 1;
    int bbase = (blockIdx.x >> 1) * 32;
    const float* emb = which ? u_embs : i_embs;
    const float* W   = (which ? w_a1 : w_c1) + (size_t)128 * 128;
    const float* bb  = which ? b_a1 : b_c1;
    int tid = threadIdx.x;

#pragma unroll 4
    for (int idx = tid; idx < 4096; idx += 512) {
        int s = idx >> 7, c = idx & 127;
        sE[idx] = (bbase + s < Btot) ? emb[(size_t)(bbase + s) * 128 + c] : 0.f;
    }
    int col = tid & 127;
    int sg  = tid >> 7;                 // samples sg*8 .. sg*8+7
    float acc[8];
#pragma unroll
    for (int j = 0; j < 8; ++j) acc[j] = bb[col];

    for (int kc = 0; kc < 4; ++kc) {
        __syncthreads();
#pragma unroll 4
        for (int idx = tid; idx < 4096; idx += 512)
            sW[idx] = W[(size_t)(kc * 32 + (idx >> 7)) * 128 + (idx & 127)];
        __syncthreads();
#pragma unroll 8
        for (int kk = 0; kk < 32; ++kk) {
            float w = sW[kk * 128 + col];
#pragma unroll
            for (int j = 0; j < 8; ++j)
                acc[j] = fmaf(sE[(sg * 8 + j) * 128 + kc * 32 + kk], w, acc[j]);
        }
    }
#pragma unroll
    for (int j = 0; j < 8; ++j) {
        int s = bbase + sg * 8 + j;
        if (s < Btot)
            g_vec[(size_t)which * Btot * 128 + (size_t)s * 128 + col] = acc[j];
    }
}

// ---------------- main kernel pieces (unchanged from R15/R16) ----------------
__device__ __forceinline__ void copy_unit(int u, uint32_t dstAddr, int tid) {
    const char* src = (const char*)g_wb + (size_t)u * 32768;
#pragma unroll
    for (int t = 0; t < 8; ++t) {
        int i = tid + t * 256;
        asm volatile("cp.async.cg.shared.global [%0], [%1], 16;"
                     :: "r"(dstAddr + i * 16), "l"(src + (size_t)i * 16));
    }
    asm volatile("cp.async.commit_group;" ::: "memory");
}

__device__ __forceinline__ void sweep(
    float (&acc)[16][4],
    uint32_t aT, uint32_t bB,
    int w, int l)
{
    const int rA = 16 * w + (l & 15);
    const uint32_t aRowOff = (uint32_t)rA * 256;
    const int axor = rA & 7;
    const int khA = l >> 4;
    const uint32_t bLane = (uint32_t)(((l >> 4) & 1) * 2048 + (l & 7) * 256);
    const int bKh  = (l >> 3) & 1;
    const int bxor = l & 7;

#pragma unroll 1
    for (int ks = 0; ks < 8; ++ks) {
        uint32_t aoff = aRowOff + (uint32_t)(((2 * ks + khA) ^ axor) << 4);
        uint32_t a0, a1, a2, a3;
        LDSM4(a0, a1, a2, a3, aT + aoff);

        uint32_t bko = bLane + (uint32_t)(((2 * ks + bKh) ^ bxor) << 4);

        uint32_t bh[8][2];
#pragma unroll
        for (int p = 0; p < 4; ++p)
            LDSM4(bh[2 * p][0], bh[2 * p][1], bh[2 * p + 1][0], bh[2 * p + 1][1],
                  bB + (uint32_t)p * 4096 + bko);
#pragma unroll
        for (int t = 0; t < 8; ++t)
            MMA(acc[t], a0, a1, a2, a3, bh[t][0], bh[t][1]);
#pragma unroll
        for (int p = 0; p < 4; ++p)
            LDSM4(bh[2 * p][0], bh[2 * p][1], bh[2 * p + 1][0], bh[2 * p + 1][1],
                  bB + (uint32_t)(p + 4) * 4096 + bko);
#pragma unroll
        for (int t = 0; t < 8; ++t)
            MMA(acc[t + 8], a0, a1, a2, a3, bh[t][0], bh[t][1]);
    }
}

__device__ __forceinline__ void gatherA(
    const float* __restrict__ tbl, const int* sIdx, char* smemc, int tid)
{
    for (int idx = tid; idx < 2048; idx += 256) {
        int r = idx >> 4;
        int c = idx & 15;
        int u = sIdx[r];
        const float4* src = (const float4*)(tbl + (size_t)u * 128 + c * 8);
        float4 v0 = src[0], v1 = src[1];
        uint4 hv = make_uint4(pkf2(v0.x, v0.y), pkf2(v0.z, v0.w),
                              pkf2(v1.x, v1.y), pkf2(v1.z, v1.w));
        *(uint4*)(smemc + SM_A + tile_off(r, c)) = hv;
    }
}

__device__ __forceinline__ void epilogueA(
    float (&acc)[16][4], char* smemc,
    const float* vec, int vstride,
    int gBase, int s_first,
    bool writeCoup, int w, int l)
{
    int q  = 16 * w + (l >> 2);
    int p2 = (l & 3) * 2;
    int r0 = q, r1 = q + 8;
    int s0 = (gBase + r0) / K_N - s_first;
    int s1 = (gBase + r1) / K_N - s_first;
    const float* bv0 = vec + s0 * vstride;
    const float* bv1 = vec + s1 * vstride;
    uint32_t* coup32 = (uint32_t*)g_coup;
#pragma unroll
    for (int t = 0; t < 16; ++t) {
        int n = 8 * t + p2;
        float y00 = fmaxf(acc[t][0] + bv0[n],     0.f);
        float y01 = fmaxf(acc[t][1] + bv0[n + 1], 0.f);
        float y10 = fmaxf(acc[t][2] + bv1[n],     0.f);
        float y11 = fmaxf(acc[t][3] + bv1[n + 1], 0.f);
        acc[t][0] = 0.f; acc[t][1] = 0.f; acc[t][2] = 0.f; acc[t][3] = 0.f;
        uint32_t h0 = pkf2(y00, y01);
        uint32_t h1 = pkf2(y10, y11);
        *(uint32_t*)(smemc + SM_A + tile_off(r0, t) + p2 * 2) = h0;
        *(uint32_t*)(smemc + SM_A + tile_off(r1, t) + p2 * 2) = h1;
        if (writeCoup) {
            coup32[(size_t)(gBase + r0) * 64 + (n >> 1)] = h0;
            coup32[(size_t)(gBase + r1) * 64 + (n >> 1)] = h1;
        }
    }
}

__device__ __forceinline__ void epilogueScore(
    float (&acc)[16][4], const float* ba2, const float* w3, float b3,
    int gBase, int w, int l)
{
    int q  = 16 * w + (l >> 2);
    int p2 = (l & 3) * 2;
    float p0 = 0.f, p1 = 0.f;
#pragma unroll
    for (int t = 0; t < 16; ++t) {
        int n = 8 * t + p2;
        p0 = fmaf(fmaxf(acc[t][0] + ba2[n],     0.f), w3[n],     p0);
        p0 = fmaf(fmaxf(acc[t][1] + ba2[n + 1], 0.f), w3[n + 1], p0);
        p1 = fmaf(fmaxf(acc[t][2] + ba2[n],     0.f), w3[n],     p1);
        p1 = fmaf(fmaxf(acc[t][3] + ba2[n + 1], 0.f), w3[n + 1], p1);
    }
    p0 += __shfl_xor_sync(0xffffffffu, p0, 1);
    p0 += __shfl_xor_sync(0xffffffffu, p0, 2);
    p1 += __shfl_xor_sync(0xffffffffu, p1, 1);
    p1 += __shfl_xor_sync(0xffffffffu, p1, 2);
    if ((l & 3) == 0) {
        g_score[gBase + q]     = p0 + b3;
        g_score[gBase + q + 8] = p1 + b3;
    }
}

#define WAITG(n) asm volatile("cp.async.wait_group %0;" :: "n"(n) : "memory")

__global__ __launch_bounds__(256, 2)
void influence_main(
    const float* __restrict__ act_users_f,
    const float* __restrict__ emb_table, const float* __restrict__ prof_table,
    const float* __restrict__ b_fus, const float* __restrict__ b_c2,
    const float* __restrict__ b_a2,  const float* __restrict__ w_a3,
    const float* __restrict__ b_a3,
    int Btot)
{
    extern __shared__ char smemc[];
    const int tid = threadIdx.x;
    const int w = tid >> 5, l = tid & 31;
    const int gBase = blockIdx.x * 128;
    const int G = Btot * K_N;
    const int s_first = gBase / K_N;
    const int* act_users = (const int*)act_users_f;
    uint32_t sb = smem_u32(smemc);

    int* sIdx     = (int*)(smemc + SM_IDX);
    float* sBfus  = (float*)(smemc + SM_BFUS);
    float* sBc2   = (float*)(smemc + SM_BC2);
    float* sBa2   = (float*)(smemc + SM_BA2);
    float* sW3    = (float*)(smemc + SM_W3);
    float* sVC1   = (float*)(smemc + SM_VC1);
    float* sVA1   = (float*)(smemc + SM_VA1);

    copy_unit(0, sb + SM_B0, tid);
    copy_unit(1, sb + SM_B1, tid);

    if (tid < 128) {
        int g = gBase + tid;
        sIdx[tid] = (g < G) ? act_users[g] : 0;
    } else {
        int c = tid - 128;
        sBfus[c] = b_fus[c];
        sBc2[c]  = b_c2[c];
        sBa2[c]  = b_a2[c];
        sW3[c]   = w_a3[c];
    }
    for (int idx = tid; idx < 4 * 128; idx += 256) {
        int j = idx >> 7, c = idx & 127;
        int s = s_first + j; if (s > Btot - 1) s = Btot - 1;
        sVC1[idx] = g_vec[(size_t)s * 128 + c];
        sVA1[idx] = g_vec[(size_t)Btot * 128 + (size_t)s * 128 + c];
    }
    __syncthreads();
    gatherA(emb_table, sIdx, smemc, tid);

    float acc[16][4];
#pragma unroll
    for (int t = 0; t < 16; ++t) {
        acc[t][0] = 0.f; acc[t][1] = 0.f; acc[t][2] = 0.f; acc[t][3] = 0.f;
    }

    WAITG(1); __syncthreads();
    sweep(acc, sb + SM_A, sb + SM_B0, w, l);
    __syncthreads();
    copy_unit(2, sb + SM_B0, tid);
    gatherA(prof_table, sIdx, smemc, tid);
    WAITG(1); __syncthreads();
    sweep(acc, sb + SM_A, sb + SM_B1, w, l);
    __syncthreads();
    copy_unit(3, sb + SM_B1, tid);
    epilogueA(acc, smemc, sBfus, 0, gBase, s_first, false, w, l);   // L1
    WAITG(1); __syncthreads();
    sweep(acc, sb + SM_A, sb + SM_B0, w, l);                        // L2
    __syncthreads();
    copy_unit(4, sb + SM_B0, tid);
    epilogueA(acc, smemc, sVC1, 128, gBase, s_first, false, w, l);  // L2 -> c1
    WAITG(1); __syncthreads();
    sweep(acc, sb + SM_A, sb + SM_B1, w, l);                        // L3
    __syncthreads();
    copy_unit(5, sb + SM_B1, tid);
    epilogueA(acc, smemc, sBc2, 0, gBase, s_first, true, w, l);     // L3 -> coup
    WAITG(1); __syncthreads();
    sweep(acc, sb + SM_A, sb + SM_B0, w, l);                        // L4
    __syncthreads();
    epilogueA(acc, smemc, sVA1, 128, gBase, s_first, false, w, l);  // L4 -> h
    WAITG(0); __syncthreads();
    sweep(acc, sb + SM_A, sb + SM_B1, w, l);                        // L5
    epilogueScore(acc, sBa2, sW3, b_a3[0], gBase, w, l);
}

// ---------------- finish: softmax + aggregation, 4 samples/block ----------------
// Thread layout: q = tid>>6 (sample in block), ht = tid&63 owns column pair
// [2ht, 2ht+2). Fully unrolled k-loop: 50 independent half2 loads in flight.
__global__ __launch_bounds__(256)
void influence_finish(
    float* __restrict__ out_combined, float* __restrict__ out_att)
{
    __shared__ float sAtt[4][64];
    int s0 = blockIdx.x * 4;
    int tid = threadIdx.x;
    int w = tid >> 5, l = tid & 31;

    // softmax: warps 0..3 handle samples 0..3
    if (w < 4) {
        int s = s0 + w;
        float v1 = (l < K_N)      ? g_score[s * K_N + l]      : -1e30f;
        float v2 = (l + 32 < K_N) ? g_score[s * K_N + l + 32] : -1e30f;
        float m = fmaxf(v1, v2);
#pragma unroll
        for (int o = 16; o; o >>= 1)
            m = fmaxf(m, __shfl_xor_sync(0xffffffffu, m, o));
        float e1 = (l < K_N)      ? expf(v1 - m) : 0.f;
        float e2 = (l + 32 < K_N) ? expf(v2 - m) : 0.f;
        float sum = e1 + e2;
#pragma unroll
        for (int o = 16; o; o >>= 1)
            sum += __shfl_xor_sync(0xffffffffu, sum, o);
        float inv = 1.f / sum;
        if (l < K_N)      sAtt[w][l]      = e1 * inv;
        if (l + 32 < K_N) sAtt[w][l + 32] = e2 * inv;
    }
    __syncthreads();

    int q  = tid >> 6;                 // sample within block
    int ht = tid & 63;                 // column-pair owner
    int s  = s0 + q;
    float a0 = 0.f, a1 = 0.f;
    const __half2* cp = (const __half2*)(g_coup + (size_t)s * K_N * 128) + ht;
#pragma unroll
    for (int k = 0; k < K_N; ++k) {
        float2 v = __half22float2(cp[(size_t)k * 64]);
        float at = sAtt[q][k];
        a0 = fmaf(at, v.x, a0);
        a1 = fmaf(at, v.y, a1);
    }
    *(float2*)(out_combined + (size_t)s * 128 + 2 * ht) = make_float2(a0, a1);
    if (ht < K_N)
        out_att[(size_t)s * K_N + ht] = sAtt[q][ht];
}

// ---------------- host launcher ----------------
extern "C" void kernel_launch(void* const* d_in, const int* in_sizes, int n_in,
                              void* d_out, int out_size) {
    const float* u_embs = (const float*)d_in[1];
    const float* i_embs = (const float*)d_in[3];
    const float* act    = (const float*)d_in[4];   // int32 data
    const float* table  = (const float*)d_in[5];
    const float* prof   = (const float*)d_in[6];
    const float* w_fus  = (const float*)d_in[7];
    const float* b_fus  = (const float*)d_in[8];
    const float* w_c1   = (const float*)d_in[9];
    const float* b_c1   = (const float*)d_in[10];
    const float* w_c2   = (const float*)d_in[11];
    const float* b_c2   = (const float*)d_in[12];
    const float* w_a1   = (const float*)d_in[13];
    const float* b_a1   = (const float*)d_in[14];
    const float* w_a2   = (const float*)d_in[15];
    const float* b_a2   = (const float*)d_in[16];
    const float* w_a3   = (const float*)d_in[17];
    const float* b_a3   = (const float*)d_in[18];

    int B = in_sizes[0];   // 4096

    float* out_combined = (float*)d_out;
    float* out_att      = out_combined + (size_t)B * 128;

    prep_w<<<48, 256>>>(w_fus, w_c1, w_c2, w_a1, w_a2);
    prep_vecs<<<((B + 31) / 32) * 2, 512>>>(i_embs, u_embs,
                                            w_c1, b_c1, w_a1, b_a1, B);

    int G = B * K_N;
    int grid = (G + 127) / 128;            // 1600 for B=4096 (exact)
    cudaFuncSetAttribute(influence_main,
                         cudaFuncAttributeMaxDynamicSharedMemorySize, SM_TOTAL);
    influence_main<<<grid, 256, SM_TOTAL>>>(
        act, table, prof,
        b_fus, b_c2, b_a2, w_a3, b_a3, B);

    influence_finish<<<B / 4, 256>>>(out_combined, out_att);
}